// round 11
// baseline (speedup 1.0000x reference)
#include <cuda_runtime.h>
#include <cuda_bf16.h>
#include <cstdint>

namespace {
constexpr int GRID = 64, NTHR = 256, ROWS = 16;
constexpr int NEVAL = 32;
// phase1: per warp N-slice 128 (16 ntiles), K=256 (16 ktiles)
// phase2: per warp N-slice 32  (4 ntiles),  K=1024 (64 ktiles)
constexpr int IMG1_N = 8 * 16 * 16 * 32;   // 65536 uint4 = 1 MB
constexpr int IMG2_N = 8 * 64 * 4 * 32;    // 65536 uint4 = 1 MB
// dynamic smem offsets (bytes)
constexpr uint32_t OFF_PROBE = 0;                       // f32 [16][260]
constexpr uint32_t OFF_HH    = 16640;                   // bf16 [16][1032]
constexpr uint32_t OFF_HL    = OFF_HH + 33024;          // 49664
constexpr uint32_t OFF_B1    = OFF_HL + 33024;          // 82688, f32[1024]
constexpr uint32_t SMEM_SZ   = OFF_B1 + 4096;           // 86784
}

__device__ __align__(16) uint4 g_img1[IMG1_N];
__device__ __align__(16) uint4 g_img2[IMG2_N];

__device__ __forceinline__ unsigned bf2pack(__nv_bfloat16 a, __nv_bfloat16 b) {
    __nv_bfloat162 t; t.x = a; t.y = b;
    return *reinterpret_cast<unsigned*>(&t);
}
__device__ __forceinline__ void split2(float x, float y, unsigned& hi, unsigned& lo) {
    const __nv_bfloat16 hx = __float2bfloat16(x), hy = __float2bfloat16(y);
    const __nv_bfloat16 lx = __float2bfloat16(x - __bfloat162float(hx));
    const __nv_bfloat16 ly = __float2bfloat16(y - __bfloat162float(hy));
    hi = bf2pack(hx, hy);
    lo = bf2pack(lx, ly);
}
__device__ __forceinline__ float tanha(float x) {
    float y; asm("tanh.approx.f32 %0, %1;" : "=f"(y) : "f"(x)); return y;
}

// ---------------- prep: weights -> per-lane fragment-order images ------------
__global__ void prep_kernel(const float* __restrict__ W1, const float* __restrict__ W2) {
    const int e = blockIdx.x * blockDim.x + threadIdx.x;
    if (e < IMG1_N) {
        const int l = e & 31, nt = (e >> 5) & 15, kt = (e >> 9) & 15, w = e >> 13;
        const int n  = w * 128 + nt * 8 + (l >> 2);
        const int k0 = kt * 16 + 2 * (l & 3);
        unsigned h0, l0, h1, l1;
        split2(W1[k0 * 1024 + n],       W1[(k0 + 1) * 1024 + n], h0, l0);
        split2(W1[(k0 + 8) * 1024 + n], W1[(k0 + 9) * 1024 + n], h1, l1);
        g_img1[e] = make_uint4(h0, h1, l0, l1);
    } else if (e < IMG1_N + IMG2_N) {
        const int e2 = e - IMG1_N;
        const int l = e2 & 31, nt = (e2 >> 5) & 3, kt = (e2 >> 7) & 63, w = e2 >> 13;
        const int n  = w * 32 + nt * 8 + (l >> 2);
        const int k0 = kt * 16 + 2 * (l & 3);
        unsigned h0, l0, h1, l1;
        split2(W2[k0 * 256 + n],       W2[(k0 + 1) * 256 + n], h0, l0);
        split2(W2[(k0 + 8) * 256 + n], W2[(k0 + 9) * 256 + n], h1, l1);
        g_img2[e2] = make_uint4(h0, h1, l0, l1);
    }
}

// D += A(bf16) * B(bf16), m16n8k16
__device__ __forceinline__ void mma16(float* d, unsigned a0, unsigned a1, unsigned a2,
                                      unsigned a3, unsigned b0, unsigned b1) {
    asm volatile(
        "mma.sync.aligned.m16n8k16.row.col.f32.bf16.bf16.f32 "
        "{%0,%1,%2,%3}, {%4,%5,%6,%7}, {%8,%9}, {%0,%1,%2,%3};"
        : "+f"(d[0]), "+f"(d[1]), "+f"(d[2]), "+f"(d[3])
        : "r"(a0), "r"(a1), "r"(a2), "r"(a3), "r"(b0), "r"(b1));
}

__global__ void __launch_bounds__(NTHR, 1) node_mma_kernel(
    const float* __restrict__ z0, const float* __restrict__ tt,
    const float* __restrict__ b2, const float* __restrict__ b1,
    float* __restrict__ out)
{
    extern __shared__ __align__(16) unsigned char sm[];
    float*  s_probe = reinterpret_cast<float*>(sm + OFF_PROBE);        // [16][260]
    unsigned short* s_hh = reinterpret_cast<unsigned short*>(sm + OFF_HH);  // [16][1032]
    unsigned short* s_hl = reinterpret_cast<unsigned short*>(sm + OFF_HL);
    float*  s_b1 = reinterpret_cast<float*>(sm + OFF_B1);

    const int tid = threadIdx.x;
    const int warp = tid >> 5, lane = tid & 31;
    const int gr = lane >> 2, tc = lane & 3;
    const int row0 = blockIdx.x * ROWS;

    const float h  = (tt[1] - tt[0]) * 0.125f;
    const float h2 = 0.5f * h, h6 = h * (1.0f / 6.0f);

    // b1 -> smem
    {
        const float4 v = reinterpret_cast<const float4*>(b1)[tid];
        reinterpret_cast<float4*>(s_b1)[tid] = v;
    }

    // phase-2 / glue ownership: cols c0(nt)=N2+8nt+2tc (+1), rows gr, gr+8
    const int N2 = warp * 32;
    float b2v[4][2], zb[4][4], ac[4][4];
    #pragma unroll
    for (int nt = 0; nt < 4; ++nt) {
        const int c0 = N2 + 8 * nt + 2 * tc;
        b2v[nt][0] = b2[c0]; b2v[nt][1] = b2[c0 + 1];
        zb[nt][0] = z0[(row0 + gr) * 256 + c0];
        zb[nt][1] = z0[(row0 + gr) * 256 + c0 + 1];
        zb[nt][2] = z0[(row0 + gr + 8) * 256 + c0];
        zb[nt][3] = z0[(row0 + gr + 8) * 256 + c0 + 1];
        *reinterpret_cast<float2*>(&s_probe[gr * 260 + c0])       = make_float2(zb[nt][0], zb[nt][1]);
        *reinterpret_cast<float2*>(&s_probe[(gr + 8) * 260 + c0]) = make_float2(zb[nt][2], zb[nt][3]);
    }
    __syncthreads();

    const int N1 = warp * 128;
    const uint4* img1w = g_img1 + warp * 8192 + lane;
    const uint4* img2w = g_img2 + warp * 8192 + lane;

    for (int ev = 0; ev < NEVAL; ++ev) {
        const int e = ev & 3;

        // ---------- phase 1: hid = tanh(probe @ W1 + b1), N-slice 128 ----------
        float a1c[16][4];
        #pragma unroll
        for (int nt = 0; nt < 16; ++nt)
            #pragma unroll
            for (int i = 0; i < 4; ++i) a1c[nt][i] = 0.0f;

        for (int kt = 0; kt < 16; ++kt) {
            const int kb = kt * 16 + 2 * tc;
            const float2 q0 = *reinterpret_cast<const float2*>(&s_probe[gr * 260 + kb]);
            const float2 q1 = *reinterpret_cast<const float2*>(&s_probe[gr * 260 + kb + 8]);
            const float2 q2 = *reinterpret_cast<const float2*>(&s_probe[(gr + 8) * 260 + kb]);
            const float2 q3 = *reinterpret_cast<const float2*>(&s_probe[(gr + 8) * 260 + kb + 8]);
            unsigned ah0, al0, ah1, al1, ah2, al2, ah3, al3;
            split2(q0.x, q0.y, ah0, al0);   // row gr,   k low
            split2(q2.x, q2.y, ah1, al1);   // row gr+8, k low
            split2(q1.x, q1.y, ah2, al2);   // row gr,   k high
            split2(q3.x, q3.y, ah3, al3);   // row gr+8, k high
            const uint4* p = img1w + kt * 512;
            #pragma unroll 4
            for (int nt = 0; nt < 16; ++nt) {
                const uint4 wv = p[nt * 32];
                mma16(a1c[nt], ah0, ah1, ah2, ah3, wv.x, wv.y);   // hi*hi
                mma16(a1c[nt], ah0, ah1, ah2, ah3, wv.z, wv.w);   // hi*lo(W)
                mma16(a1c[nt], al0, al1, al2, al3, wv.x, wv.y);   // lo(A)*hi
            }
        }
        #pragma unroll
        for (int nt = 0; nt < 16; ++nt) {
            const int c0 = N1 + 8 * nt + 2 * tc;
            const float v0 = tanha(a1c[nt][0] + s_b1[c0]);
            const float v1 = tanha(a1c[nt][1] + s_b1[c0 + 1]);
            const float v2 = tanha(a1c[nt][2] + s_b1[c0]);
            const float v3 = tanha(a1c[nt][3] + s_b1[c0 + 1]);
            unsigned hiA, loA, hiB, loB;
            split2(v0, v1, hiA, loA);
            split2(v2, v3, hiB, loB);
            *reinterpret_cast<unsigned*>(&s_hh[gr * 1032 + c0])       = hiA;
            *reinterpret_cast<unsigned*>(&s_hl[gr * 1032 + c0])       = loA;
            *reinterpret_cast<unsigned*>(&s_hh[(gr + 8) * 1032 + c0]) = hiB;
            *reinterpret_cast<unsigned*>(&s_hl[(gr + 8) * 1032 + c0]) = loB;
        }
        __syncthreads();

        // ---------- phase 2: k = hid @ W2 + b2, N-slice 32 ----------
        float a2c[4][4];
        #pragma unroll
        for (int nt = 0; nt < 4; ++nt)
            #pragma unroll
            for (int i = 0; i < 4; ++i) a2c[nt][i] = 0.0f;

        for (int kt = 0; kt < 64; ++kt) {
            const int kb = kt * 16 + 2 * tc;
            const unsigned ah0 = *reinterpret_cast<const unsigned*>(&s_hh[gr * 1032 + kb]);
            const unsigned ah1 = *reinterpret_cast<const unsigned*>(&s_hh[(gr + 8) * 1032 + kb]);
            const unsigned ah2 = *reinterpret_cast<const unsigned*>(&s_hh[gr * 1032 + kb + 8]);
            const unsigned ah3 = *reinterpret_cast<const unsigned*>(&s_hh[(gr + 8) * 1032 + kb + 8]);
            const unsigned al0 = *reinterpret_cast<const unsigned*>(&s_hl[gr * 1032 + kb]);
            const unsigned al1 = *reinterpret_cast<const unsigned*>(&s_hl[(gr + 8) * 1032 + kb]);
            const unsigned al2 = *reinterpret_cast<const unsigned*>(&s_hl[gr * 1032 + kb + 8]);
            const unsigned al3 = *reinterpret_cast<const unsigned*>(&s_hl[(gr + 8) * 1032 + kb + 8]);
            const uint4* p = img2w + kt * 128;
            #pragma unroll
            for (int nt = 0; nt < 4; ++nt) {
                const uint4 wv = p[nt * 32];
                mma16(a2c[nt], ah0, ah1, ah2, ah3, wv.x, wv.y);
                mma16(a2c[nt], ah0, ah1, ah2, ah3, wv.z, wv.w);
                mma16(a2c[nt], al0, al1, al2, al3, wv.x, wv.y);
            }
        }

        // ---------- RK4 glue (registers) + probe rebuild ----------
        #pragma unroll
        for (int nt = 0; nt < 4; ++nt) {
            float p[4];
            #pragma unroll
            for (int i = 0; i < 4; ++i) {
                const float kv = a2c[nt][i] + b2v[nt][i & 1];
                if (e == 0)      { ac[nt][i] = kv;                          p[i] = fmaf(h2, kv, zb[nt][i]); }
                else if (e == 1) { ac[nt][i] = fmaf(2.0f, kv, ac[nt][i]);   p[i] = fmaf(h2, kv, zb[nt][i]); }
                else if (e == 2) { ac[nt][i] = fmaf(2.0f, kv, ac[nt][i]);   p[i] = fmaf(h, kv, zb[nt][i]); }
                else             { ac[nt][i] += kv; zb[nt][i] = fmaf(h6, ac[nt][i], zb[nt][i]); p[i] = zb[nt][i]; }
            }
            const int c0 = N2 + 8 * nt + 2 * tc;
            *reinterpret_cast<float2*>(&s_probe[gr * 260 + c0])       = make_float2(p[0], p[1]);
            *reinterpret_cast<float2*>(&s_probe[(gr + 8) * 260 + c0]) = make_float2(p[2], p[3]);
        }
        __syncthreads();
    }

    #pragma unroll
    for (int nt = 0; nt < 4; ++nt) {
        const int c0 = N2 + 8 * nt + 2 * tc;
        out[(row0 + gr) * 256 + c0]         = zb[nt][0];
        out[(row0 + gr) * 256 + c0 + 1]     = zb[nt][1];
        out[(row0 + gr + 8) * 256 + c0]     = zb[nt][2];
        out[(row0 + gr + 8) * 256 + c0 + 1] = zb[nt][3];
    }
}

extern "C" void kernel_launch(void* const* d_in, const int* in_sizes, int n_in,
                              void* d_out, int out_size) {
    const float* z0 = (const float*)d_in[0];
    const float* tt = (const float*)d_in[1];
    const float* W1 = (const float*)d_in[2];
    const float* b1 = (const float*)d_in[3];
    const float* W2 = (const float*)d_in[4];
    const float* b2 = (const float*)d_in[5];
    float* out = (float*)d_out;
    (void)in_sizes; (void)n_in; (void)out_size;

    static bool attr_set = false;
    if (!attr_set) {
        cudaFuncSetAttribute(node_mma_kernel, cudaFuncAttributeMaxDynamicSharedMemorySize,
                             (int)SMEM_SZ);
        attr_set = true;
    }
    prep_kernel<<<(IMG1_N + IMG2_N) / 256, 256>>>(W1, W2);
    node_mma_kernel<<<GRID, NTHR, SMEM_SZ>>>(z0, tt, b2, b1, out);
}

// round 12
// speedup vs baseline: 1.8725x; 1.8725x over previous
#include <cuda_runtime.h>
#include <cuda_bf16.h>
#include <cstdint>

namespace {
constexpr int GRID = 64, NTHR = 512, ROWS = 16;
constexpr int NEVAL = 32;
// phase1: per warp N-slice 64 (8 ntiles of n8), K=256 (16 ktiles)
// phase2: per warp N-slice 16 (2 ntiles),      K=1024 (64 ktiles)
constexpr int IMG1_N = 16 * 128 * 32;   // kt * g * lane = 65536 uint4 (1 MB)
constexpr int IMG2_N = 64 * 32 * 32;    // 65536 uint4 (1 MB)
constexpr uint32_t OFF_PROBE = 0;                 // f32 [16][260]
constexpr uint32_t OFF_HH    = 16640;             // bf16 [16][1032]
constexpr uint32_t OFF_HL    = OFF_HH + 33024;    // 49664
constexpr uint32_t OFF_B1    = OFF_HL + 33024;    // 82688
constexpr uint32_t SMEM_SZ   = OFF_B1 + 4096;     // 86784
}

__device__ __align__(16) uint4 g_img1[IMG1_N];
__device__ __align__(16) uint4 g_img2[IMG2_N];

__device__ __forceinline__ unsigned bf2pack(__nv_bfloat16 a, __nv_bfloat16 b) {
    __nv_bfloat162 t; t.x = a; t.y = b;
    return *reinterpret_cast<unsigned*>(&t);
}
__device__ __forceinline__ void split2(float x, float y, unsigned& hi, unsigned& lo) {
    const __nv_bfloat16 hx = __float2bfloat16(x), hy = __float2bfloat16(y);
    const __nv_bfloat16 lx = __float2bfloat16(x - __bfloat162float(hx));
    const __nv_bfloat16 ly = __float2bfloat16(y - __bfloat162float(hy));
    hi = bf2pack(hx, hy);
    lo = bf2pack(lx, ly);
}
__device__ __forceinline__ float tanha(float x) {
    float y; asm("tanh.approx.f32 %0, %1;" : "=f"(y) : "f"(x)); return y;
}

// ---------------- prep: weights -> per-lane fragment-order images ------------
// img1[kt][g][lane]: n = g*8 + (l>>2), k0 = kt*16 + 2*(l&3)
// uint4 = { hi(k0,k0+1), hi(k0+8,k0+9), lo(k0,k0+1), lo(k0+8,k0+9) }
__global__ void prep_kernel(const float* __restrict__ W1, const float* __restrict__ W2) {
    const int e = blockIdx.x * blockDim.x + threadIdx.x;
    if (e < IMG1_N) {
        const int l = e & 31, g = (e >> 5) & 127, kt = e >> 12;
        const int n  = g * 8 + (l >> 2);
        const int k0 = kt * 16 + 2 * (l & 3);
        unsigned h0, l0, h1, l1;
        split2(W1[k0 * 1024 + n],       W1[(k0 + 1) * 1024 + n], h0, l0);
        split2(W1[(k0 + 8) * 1024 + n], W1[(k0 + 9) * 1024 + n], h1, l1);
        g_img1[e] = make_uint4(h0, h1, l0, l1);
    } else if (e < IMG1_N + IMG2_N) {
        const int e2 = e - IMG1_N;
        const int l = e2 & 31, g = (e2 >> 5) & 31, kt = e2 >> 10;
        const int n  = g * 8 + (l >> 2);
        const int k0 = kt * 16 + 2 * (l & 3);
        unsigned h0, l0, h1, l1;
        split2(W2[k0 * 256 + n],       W2[(k0 + 1) * 256 + n], h0, l0);
        split2(W2[(k0 + 8) * 256 + n], W2[(k0 + 9) * 256 + n], h1, l1);
        g_img2[e2] = make_uint4(h0, h1, l0, l1);
    }
}

__device__ __forceinline__ void mma16(float* d, unsigned a0, unsigned a1, unsigned a2,
                                      unsigned a3, unsigned b0, unsigned b1) {
    asm volatile(
        "mma.sync.aligned.m16n8k16.row.col.f32.bf16.bf16.f32 "
        "{%0,%1,%2,%3}, {%4,%5,%6,%7}, {%8,%9}, {%0,%1,%2,%3};"
        : "+f"(d[0]), "+f"(d[1]), "+f"(d[2]), "+f"(d[3])
        : "r"(a0), "r"(a1), "r"(a2), "r"(a3), "r"(b0), "r"(b1));
}

__global__ void __launch_bounds__(NTHR, 1) node_mma_kernel(
    const float* __restrict__ z0, const float* __restrict__ tt,
    const float* __restrict__ b2, const float* __restrict__ b1,
    float* __restrict__ out)
{
    extern __shared__ __align__(16) unsigned char sm[];
    float* s_probe = reinterpret_cast<float*>(sm + OFF_PROBE);             // [16][260]
    unsigned short* s_hh = reinterpret_cast<unsigned short*>(sm + OFF_HH); // [16][1032]
    unsigned short* s_hl = reinterpret_cast<unsigned short*>(sm + OFF_HL);
    float* s_b1 = reinterpret_cast<float*>(sm + OFF_B1);

    const int tid = threadIdx.x;
    const int warp = tid >> 5, lane = tid & 31;
    const int gr = lane >> 2, tc = lane & 3;
    const int row0 = blockIdx.x * ROWS;

    const float h  = (tt[1] - tt[0]) * 0.125f;
    const float h2 = 0.5f * h, h6 = h * (1.0f / 6.0f);

    if (tid < 256) {
        const float4 v = reinterpret_cast<const float4*>(b1)[tid];
        reinterpret_cast<float4*>(s_b1)[tid] = v;
    }

    // phase-2 / glue ownership: N-slice 16 at N2 = warp*16
    const int N2 = warp * 16;
    float b2v[2][2], zb[2][4], ac[2][4];
    #pragma unroll
    for (int nt = 0; nt < 2; ++nt) {
        const int c0 = N2 + 8 * nt + 2 * tc;
        b2v[nt][0] = b2[c0]; b2v[nt][1] = b2[c0 + 1];
        zb[nt][0] = z0[(row0 + gr) * 256 + c0];
        zb[nt][1] = z0[(row0 + gr) * 256 + c0 + 1];
        zb[nt][2] = z0[(row0 + gr + 8) * 256 + c0];
        zb[nt][3] = z0[(row0 + gr + 8) * 256 + c0 + 1];
        *reinterpret_cast<float2*>(&s_probe[gr * 260 + c0])       = make_float2(zb[nt][0], zb[nt][1]);
        *reinterpret_cast<float2*>(&s_probe[(gr + 8) * 260 + c0]) = make_float2(zb[nt][2], zb[nt][3]);
    }
    __syncthreads();

    const int N1 = warp * 64;                               // phase-1 N-slice base
    const uint4* img1w = g_img1 + (warp * 8) * 32 + lane;   // + kt*4096 + g*32
    const uint4* img2w = g_img2 + (warp * 2) * 32 + lane;   // + kt*1024 + g*32

    for (int ev = 0; ev < NEVAL; ++ev) {
        const int e = ev & 3;

        // ---------- phase 1: hid = tanh(probe @ W1 + b1), N-slice 64 ----------
        float a1c[8][4];
        #pragma unroll
        for (int nt = 0; nt < 8; ++nt)
            #pragma unroll
            for (int i = 0; i < 4; ++i) a1c[nt][i] = 0.0f;

        uint4 cur[8], nxt[8];
        #pragma unroll
        for (int g = 0; g < 8; ++g) cur[g] = img1w[g * 32];

        #pragma unroll
        for (int kt = 0; kt < 16; ++kt) {
            if (kt < 15) {
                #pragma unroll
                for (int g = 0; g < 8; ++g) nxt[g] = img1w[(kt + 1) * 4096 + g * 32];
            }
            const int kb = kt * 16 + 2 * tc;
            const float2 q0 = *reinterpret_cast<const float2*>(&s_probe[gr * 260 + kb]);
            const float2 q1 = *reinterpret_cast<const float2*>(&s_probe[gr * 260 + kb + 8]);
            const float2 q2 = *reinterpret_cast<const float2*>(&s_probe[(gr + 8) * 260 + kb]);
            const float2 q3 = *reinterpret_cast<const float2*>(&s_probe[(gr + 8) * 260 + kb + 8]);
            unsigned ah0, al0, ah1, al1, ah2, al2, ah3, al3;
            split2(q0.x, q0.y, ah0, al0);
            split2(q2.x, q2.y, ah1, al1);
            split2(q1.x, q1.y, ah2, al2);
            split2(q3.x, q3.y, ah3, al3);
            #pragma unroll
            for (int g = 0; g < 8; ++g) {
                const uint4 wv = cur[g];
                mma16(a1c[g], ah0, ah1, ah2, ah3, wv.x, wv.y);   // hi*hi
                mma16(a1c[g], ah0, ah1, ah2, ah3, wv.z, wv.w);   // hi*Wlo
                mma16(a1c[g], al0, al1, al2, al3, wv.x, wv.y);   // Alo*hi
            }
            #pragma unroll
            for (int g = 0; g < 8; ++g) cur[g] = nxt[g];
        }

        #pragma unroll
        for (int nt = 0; nt < 8; ++nt) {
            const int c0 = N1 + 8 * nt + 2 * tc;
            const float v0 = tanha(a1c[nt][0] + s_b1[c0]);
            const float v1 = tanha(a1c[nt][1] + s_b1[c0 + 1]);
            const float v2 = tanha(a1c[nt][2] + s_b1[c0]);
            const float v3 = tanha(a1c[nt][3] + s_b1[c0 + 1]);
            unsigned hiA, loA, hiB, loB;
            split2(v0, v1, hiA, loA);
            split2(v2, v3, hiB, loB);
            *reinterpret_cast<unsigned*>(&s_hh[gr * 1032 + c0])       = hiA;
            *reinterpret_cast<unsigned*>(&s_hl[gr * 1032 + c0])       = loA;
            *reinterpret_cast<unsigned*>(&s_hh[(gr + 8) * 1032 + c0]) = hiB;
            *reinterpret_cast<unsigned*>(&s_hl[(gr + 8) * 1032 + c0]) = loB;
        }
        __syncthreads();

        // ---------- phase 2: k = hid @ W2 + b2, N-slice 16 ----------
        float a2c[2][4];
        #pragma unroll
        for (int nt = 0; nt < 2; ++nt)
            #pragma unroll
            for (int i = 0; i < 4; ++i) a2c[nt][i] = 0.0f;

        uint4 c2[2], n2[2];
        c2[0] = img2w[0]; c2[1] = img2w[32];

        #pragma unroll 4
        for (int kt = 0; kt < 64; ++kt) {
            if (kt < 63) {
                n2[0] = img2w[(kt + 1) * 1024];
                n2[1] = img2w[(kt + 1) * 1024 + 32];
            }
            const int kb = kt * 16 + 2 * tc;
            const unsigned ah0 = *reinterpret_cast<const unsigned*>(&s_hh[gr * 1032 + kb]);
            const unsigned ah1 = *reinterpret_cast<const unsigned*>(&s_hh[(gr + 8) * 1032 + kb]);
            const unsigned ah2 = *reinterpret_cast<const unsigned*>(&s_hh[gr * 1032 + kb + 8]);
            const unsigned ah3 = *reinterpret_cast<const unsigned*>(&s_hh[(gr + 8) * 1032 + kb + 8]);
            const unsigned al0 = *reinterpret_cast<const unsigned*>(&s_hl[gr * 1032 + kb]);
            const unsigned al1 = *reinterpret_cast<const unsigned*>(&s_hl[(gr + 8) * 1032 + kb]);
            const unsigned al2 = *reinterpret_cast<const unsigned*>(&s_hl[gr * 1032 + kb + 8]);
            const unsigned al3 = *reinterpret_cast<const unsigned*>(&s_hl[(gr + 8) * 1032 + kb + 8]);
            #pragma unroll
            for (int nt = 0; nt < 2; ++nt) {
                const uint4 wv = c2[nt];
                mma16(a2c[nt], ah0, ah1, ah2, ah3, wv.x, wv.y);
                mma16(a2c[nt], ah0, ah1, ah2, ah3, wv.z, wv.w);
                mma16(a2c[nt], al0, al1, al2, al3, wv.x, wv.y);
            }
            c2[0] = n2[0]; c2[1] = n2[1];
        }

        // ---------- RK4 glue + probe rebuild ----------
        #pragma unroll
        for (int nt = 0; nt < 2; ++nt) {
            float p[4];
            #pragma unroll
            for (int i = 0; i < 4; ++i) {
                const float kv = a2c[nt][i] + b2v[nt][i & 1];
                if (e == 0)      { ac[nt][i] = kv;                          p[i] = fmaf(h2, kv, zb[nt][i]); }
                else if (e == 1) { ac[nt][i] = fmaf(2.0f, kv, ac[nt][i]);   p[i] = fmaf(h2, kv, zb[nt][i]); }
                else if (e == 2) { ac[nt][i] = fmaf(2.0f, kv, ac[nt][i]);   p[i] = fmaf(h, kv, zb[nt][i]); }
                else             { ac[nt][i] += kv; zb[nt][i] = fmaf(h6, ac[nt][i], zb[nt][i]); p[i] = zb[nt][i]; }
            }
            const int c0 = N2 + 8 * nt + 2 * tc;
            *reinterpret_cast<float2*>(&s_probe[gr * 260 + c0])       = make_float2(p[0], p[1]);
            *reinterpret_cast<float2*>(&s_probe[(gr + 8) * 260 + c0]) = make_float2(p[2], p[3]);
        }
        __syncthreads();
    }

    #pragma unroll
    for (int nt = 0; nt < 2; ++nt) {
        const int c0 = N2 + 8 * nt + 2 * tc;
        out[(row0 + gr) * 256 + c0]         = zb[nt][0];
        out[(row0 + gr) * 256 + c0 + 1]     = zb[nt][1];
        out[(row0 + gr + 8) * 256 + c0]     = zb[nt][2];
        out[(row0 + gr + 8) * 256 + c0 + 1] = zb[nt][3];
    }
}

extern "C" void kernel_launch(void* const* d_in, const int* in_sizes, int n_in,
                              void* d_out, int out_size) {
    const float* z0 = (const float*)d_in[0];
    const float* tt = (const float*)d_in[1];
    const float* W1 = (const float*)d_in[2];
    const float* b1 = (const float*)d_in[3];
    const float* W2 = (const float*)d_in[4];
    const float* b2 = (const float*)d_in[5];
    float* out = (float*)d_out;
    (void)in_sizes; (void)n_in; (void)out_size;

    static bool attr_set = false;
    if (!attr_set) {
        cudaFuncSetAttribute(node_mma_kernel, cudaFuncAttributeMaxDynamicSharedMemorySize,
                             (int)SMEM_SZ);
        attr_set = true;
    }
    prep_kernel<<<(IMG1_N + IMG2_N) / 256, 256>>>(W1, W2);
    node_mma_kernel<<<GRID, NTHR, SMEM_SZ>>>(z0, tt, b2, b1, out);
}